// round 3
// baseline (speedup 1.0000x reference)
#include <cuda_runtime.h>
#include <stdint.h>

#define N_NODES 50000
#define N_EDGES 1000000
#define IN_F 128
#define OUT_F 64
#define TILE_ROWS 128

// Static scratch (no allocations allowed)
__device__ float              g_support[N_NODES * OUT_F];   // features @ W
__device__ int                g_rowptr[N_NODES + 1];        // CSR row pointers (by dst)
__device__ int                g_cursor[N_NODES];            // counts, then write cursors
__device__ unsigned long long g_csr[N_EDGES];               // packed (w<<32 | src)

// ---------------------------------------------------------------------------
// Kernel 1: register-tiled GEMM  support = features @ W
// ---------------------------------------------------------------------------
__global__ __launch_bounds__(256) void gemm_kernel(
    const float* __restrict__ feat,
    const float* __restrict__ W,
    float* __restrict__ support)
{
    __shared__ float Ws[IN_F][OUT_F];     // 32 KB
    __shared__ float Fs[TILE_ROWS][16];   // 8 KB

    const int tid = threadIdx.x;

    {   // full W into smem: 2048 float4, 8 per thread
        const float4* Wv = reinterpret_cast<const float4*>(W);
        float4* Wsv = reinterpret_cast<float4*>(&Ws[0][0]);
        #pragma unroll
        for (int i = 0; i < 8; i++)
            Wsv[tid + i * 256] = Wv[tid + i * 256];
    }

    const int row_base = blockIdx.x * TILE_ROWS;
    const int cg = tid & 15;     // cols [4*cg, 4*cg+4)
    const int rg = tid >> 4;     // rows [8*rg, 8*rg+8)

    float acc[8][4] = {};

    #pragma unroll 1
    for (int kc = 0; kc < IN_F / 16; kc++) {
        __syncthreads();
        #pragma unroll
        for (int i = 0; i < 2; i++) {
            int idx = tid + i * 256;
            int row = idx >> 2;
            int q = idx & 3;
            int grow = row_base + row;
            float4 v = make_float4(0.f, 0.f, 0.f, 0.f);
            if (grow < N_NODES)
                v = *reinterpret_cast<const float4*>(
                        feat + (size_t)grow * IN_F + kc * 16 + q * 4);
            *reinterpret_cast<float4*>(&Fs[row][q * 4]) = v;
        }
        __syncthreads();

        #pragma unroll
        for (int kk = 0; kk < 16; kk++) {
            const int k = kc * 16 + kk;
            const float4 w4 = *reinterpret_cast<const float4*>(&Ws[k][cg * 4]);
            #pragma unroll
            for (int r = 0; r < 8; r++) {
                const float f = Fs[rg * 8 + r][kk];
                acc[r][0] += f * w4.x;
                acc[r][1] += f * w4.y;
                acc[r][2] += f * w4.z;
                acc[r][3] += f * w4.w;
            }
        }
    }

    #pragma unroll
    for (int r = 0; r < 8; r++) {
        const int grow = row_base + rg * 8 + r;
        if (grow < N_NODES)
            *reinterpret_cast<float4*>(support + (size_t)grow * OUT_F + cg * 4) =
                make_float4(acc[r][0], acc[r][1], acc[r][2], acc[r][3]);
    }
}

// ---------------------------------------------------------------------------
// Kernel 2: histogram of dst degrees into g_cursor (zeroed by memset node)
// ---------------------------------------------------------------------------
__global__ __launch_bounds__(256) void hist_kernel(
    const int* __restrict__ edge_dst, int* __restrict__ count)
{
    const int e = blockIdx.x * blockDim.x + threadIdx.x;
    if (e < N_EDGES) atomicAdd(&count[edge_dst[e]], 1);
}

// ---------------------------------------------------------------------------
// Kernel 3: single-block exclusive scan of 50K counts.
// Writes exclusive prefix to BOTH g_rowptr and g_cursor.
// ---------------------------------------------------------------------------
#define SCAN_T 1024
#define SCAN_EPT 8
#define SCAN_CHUNK (SCAN_T * SCAN_EPT)          // 8192
#define SCAN_NCHUNK ((N_NODES + SCAN_CHUNK - 1) / SCAN_CHUNK)  // 7

__global__ __launch_bounds__(SCAN_T) void scan_kernel(
    int* __restrict__ count,      // g_cursor (input), overwritten with excl
    int* __restrict__ rowptr)     // g_rowptr
{
    __shared__ int partials[SCAN_T];
    const int t = threadIdx.x;
    int carry = 0;

    for (int c = 0; c < SCAN_NCHUNK; c++) {
        const int idx0 = c * SCAN_CHUNK + t * SCAN_EPT;
        int v[SCAN_EPT];
        #pragma unroll
        for (int i = 0; i < SCAN_EPT; i++)
            v[i] = (idx0 + i < N_NODES) ? count[idx0 + i] : 0;
        #pragma unroll
        for (int i = 1; i < SCAN_EPT; i++) v[i] += v[i - 1];   // local inclusive

        partials[t] = v[SCAN_EPT - 1];
        __syncthreads();
        for (int off = 1; off < SCAN_T; off <<= 1) {
            int x = (t >= off) ? partials[t - off] : 0;
            __syncthreads();
            partials[t] += x;
            __syncthreads();
        }
        const int excl = carry + ((t > 0) ? partials[t - 1] : 0);
        #pragma unroll
        for (int i = 0; i < SCAN_EPT; i++) {
            if (idx0 + i < N_NODES) {
                const int ex = excl + ((i > 0) ? v[i - 1] : 0);
                rowptr[idx0 + i] = ex;
                count[idx0 + i]  = ex;   // cursor copy
            }
        }
        const int tot = partials[SCAN_T - 1];
        __syncthreads();
        carry += tot;
    }
    if (t == 0) rowptr[N_NODES] = carry;
}

// ---------------------------------------------------------------------------
// Kernel 4: permute edges into CSR order; pack (w, src) into 8 bytes.
// ---------------------------------------------------------------------------
__global__ __launch_bounds__(256) void permute_kernel(
    const int* __restrict__ edge_src,
    const int* __restrict__ edge_dst,
    const float* __restrict__ edge_w,
    int* __restrict__ cursor,
    unsigned long long* __restrict__ csr)
{
    const int e = blockIdx.x * blockDim.x + threadIdx.x;
    if (e >= N_EDGES) return;
    const int s = edge_src[e];
    const int d = edge_dst[e];
    const float w = edge_w[e];
    const int slot = atomicAdd(&cursor[d], 1);
    csr[slot] = ((unsigned long long)__float_as_uint(w) << 32) | (unsigned)s;
}

// ---------------------------------------------------------------------------
// Kernel 5: CSR gather. One warp per dst node; lane owns float2 column pair.
// No atomics: register accumulation, single store with bias folded in.
// ---------------------------------------------------------------------------
__global__ __launch_bounds__(256) void gather_kernel(
    const unsigned long long* __restrict__ csr,
    const int* __restrict__ rowptr,
    const float* __restrict__ support,
    const float* __restrict__ b,
    float* __restrict__ out)
{
    const int node = blockIdx.x * 8 + (threadIdx.x >> 5);
    if (node >= N_NODES) return;
    const int lane = threadIdx.x & 31;

    const int beg = rowptr[node];
    const int end = rowptr[node + 1];

    float2 acc = make_float2(0.f, 0.f);

    for (int p = beg; p < end; p += 32) {
        const int myi = p + lane;
        unsigned long long rec = (myi < end) ? csr[myi] : 0ull;
        const int cnt = min(32, end - p);
        for (int j = 0; j < cnt; j++) {
            const unsigned long long r = __shfl_sync(0xFFFFFFFFu, rec, j);
            const int   s = (int)(r & 0xFFFFFFFFull);
            const float w = __uint_as_float((unsigned)(r >> 32));
            const float2 sv = *reinterpret_cast<const float2*>(
                support + (size_t)s * OUT_F + lane * 2);
            acc.x += w * sv.x;
            acc.y += w * sv.y;
        }
    }

    const float2 b2 = reinterpret_cast<const float2*>(b)[lane];
    acc.x += b2.x;
    acc.y += b2.y;
    reinterpret_cast<float2*>(out + (size_t)node * OUT_F)[lane] = acc;
}

// ---------------------------------------------------------------------------
extern "C" void kernel_launch(void* const* d_in, const int* in_sizes, int n_in,
                              void* d_out, int out_size)
{
    const float* features = (const float*)d_in[0];
    const int*   edge_src = (const int*)d_in[1];
    const int*   edge_dst = (const int*)d_in[2];
    const float* edge_w   = (const float*)d_in[3];
    const float* W        = (const float*)d_in[4];
    const float* b        = (const float*)d_in[5];
    float* out = (float*)d_out;

    float* support;            cudaGetSymbolAddress((void**)&support, g_support);
    int* rowptr;               cudaGetSymbolAddress((void**)&rowptr, g_rowptr);
    int* cursor;               cudaGetSymbolAddress((void**)&cursor, g_cursor);
    unsigned long long* csr;   cudaGetSymbolAddress((void**)&csr, g_csr);

    const int eblocks = (N_EDGES + 255) / 256;

    // 1) support = features @ W
    gemm_kernel<<<(N_NODES + TILE_ROWS - 1) / TILE_ROWS, 256>>>(features, W, support);

    // 2) CSR build by dst
    cudaMemsetAsync(cursor, 0, N_NODES * sizeof(int));
    hist_kernel<<<eblocks, 256>>>(edge_dst, cursor);
    scan_kernel<<<1, SCAN_T>>>(cursor, rowptr);
    permute_kernel<<<eblocks, 256>>>(edge_src, edge_dst, edge_w, cursor, csr);

    // 3) gather + bias
    gather_kernel<<<(N_NODES + 7) / 8, 256>>>(csr, rowptr, support, b, out);
}

// round 4
// speedup vs baseline: 1.9233x; 1.9233x over previous
#include <cuda_runtime.h>
#include <stdint.h>

#define N_NODES 50000
#define N_EDGES 1000000
#define IN_F 128
#define OUT_F 64
#define TILE_ROWS 128

// Scratch: support = features @ W  [N_NODES, OUT_F]
__device__ float g_support[N_NODES * OUT_F];

// ---------------------------------------------------------------------------
// Kernel 1: register-tiled GEMM  support = features @ W, fused out = b init.
// Block: 256 threads, tile 128 rows x 64 cols. Per thread: 8 rows x 4 cols.
// W fully staged in smem (32KB). Fs double-buffered in 16-wide k-chunks via
// register staging so chunk k+1's global loads overlap chunk k's FFMAs.
// ---------------------------------------------------------------------------
__global__ __launch_bounds__(256) void gemm_bias_kernel(
    const float* __restrict__ feat,   // [N_NODES, IN_F]
    const float* __restrict__ W,      // [IN_F, OUT_F]
    const float* __restrict__ b,      // [OUT_F]
    float* __restrict__ support,      // [N_NODES, OUT_F]
    float* __restrict__ out)          // [N_NODES, OUT_F]
{
    __shared__ float Ws[IN_F][OUT_F];        // 32 KB
    __shared__ float Fs[2][TILE_ROWS][16];   // 16 KB (double-buffered chunk)

    const int tid = threadIdx.x;
    const int row_base = blockIdx.x * TILE_ROWS;

    // Each thread stages 2 float4 of the feature chunk per iteration.
    const int idx0 = tid;            // 0..255
    const int idx1 = tid + 256;      // 256..511
    const int frow0 = idx0 >> 2, fq0 = idx0 & 3;
    const int frow1 = idx1 >> 2, fq1 = idx1 & 3;
    const int grow0 = row_base + frow0;
    const int grow1 = row_base + frow1;

    // Cooperative load of full W: 2048 float4, 8 per thread
    {
        const float4* Wv = reinterpret_cast<const float4*>(W);
        float4* Wsv = reinterpret_cast<float4*>(&Ws[0][0]);
        #pragma unroll
        for (int i = 0; i < 8; i++)
            Wsv[tid + i * 256] = Wv[tid + i * 256];
    }

    // Prefetch chunk 0 into registers
    float4 p0 = make_float4(0.f, 0.f, 0.f, 0.f);
    float4 p1 = make_float4(0.f, 0.f, 0.f, 0.f);
    if (grow0 < N_NODES)
        p0 = *reinterpret_cast<const float4*>(feat + (size_t)grow0 * IN_F + fq0 * 4);
    if (grow1 < N_NODES)
        p1 = *reinterpret_cast<const float4*>(feat + (size_t)grow1 * IN_F + fq1 * 4);
    *reinterpret_cast<float4*>(&Fs[0][frow0][fq0 * 4]) = p0;
    *reinterpret_cast<float4*>(&Fs[0][frow1][fq1 * 4]) = p1;
    __syncthreads();

    const int cg = tid & 15;     // cols [4*cg, 4*cg+4)
    const int rg = tid >> 4;     // rows [8*rg, 8*rg+8)

    float acc[8][4] = {};

    #pragma unroll 1
    for (int kc = 0; kc < IN_F / 16; kc++) {
        // Issue next chunk's loads early (overlap with FFMAs below)
        if (kc + 1 < IN_F / 16) {
            p0 = make_float4(0.f, 0.f, 0.f, 0.f);
            p1 = make_float4(0.f, 0.f, 0.f, 0.f);
            const int koff = (kc + 1) * 16;
            if (grow0 < N_NODES)
                p0 = *reinterpret_cast<const float4*>(
                        feat + (size_t)grow0 * IN_F + koff + fq0 * 4);
            if (grow1 < N_NODES)
                p1 = *reinterpret_cast<const float4*>(
                        feat + (size_t)grow1 * IN_F + koff + fq1 * 4);
        }

        const int buf = kc & 1;
        #pragma unroll
        for (int kk = 0; kk < 16; kk++) {
            const int k = kc * 16 + kk;
            const float4 w4 = *reinterpret_cast<const float4*>(&Ws[k][cg * 4]);
            #pragma unroll
            for (int r = 0; r < 8; r++) {
                const float f = Fs[buf][rg * 8 + r][kk];
                acc[r][0] += f * w4.x;
                acc[r][1] += f * w4.y;
                acc[r][2] += f * w4.z;
                acc[r][3] += f * w4.w;
            }
        }

        if (kc + 1 < IN_F / 16) {
            __syncthreads();   // everyone done reading buf before overwrite? no:
                               // we overwrite buf^1 which was consumed 1 iter ago;
                               // barrier orders stores of next buf vs reads of it.
            *reinterpret_cast<float4*>(&Fs[buf ^ 1][frow0][fq0 * 4]) = p0;
            *reinterpret_cast<float4*>(&Fs[buf ^ 1][frow1][fq1 * 4]) = p1;
            __syncthreads();
        }
    }

    // Epilogue: store support tile; initialize out tile with bias.
    const float4 b4 = *reinterpret_cast<const float4*>(b + cg * 4);
    #pragma unroll
    for (int r = 0; r < 8; r++) {
        const int grow = row_base + rg * 8 + r;
        if (grow < N_NODES) {
            *reinterpret_cast<float4*>(support + (size_t)grow * OUT_F + cg * 4) =
                make_float4(acc[r][0], acc[r][1], acc[r][2], acc[r][3]);
            *reinterpret_cast<float4*>(out + (size_t)grow * OUT_F + cg * 4) = b4;
        }
    }
}

// ---------------------------------------------------------------------------
// Kernel 2: edge scatter with vector reductions.
// Block = 256 threads = 8 warps, 128 edges staged in smem. Each warp:
// 2 edges per iteration (16 lanes x float4 = 64 cols), 8 unrolled iterations
// -> 8 independent LDG.128 in flight per thread before the REDG.v4s retire.
// ---------------------------------------------------------------------------
__global__ __launch_bounds__(256) void scatter_kernel(
    const int* __restrict__ edge_src,
    const int* __restrict__ edge_dst,
    const float* __restrict__ edge_w,
    const float* __restrict__ support,
    float* __restrict__ out)
{
    __shared__ int   s_src[128];
    __shared__ int   s_dst[128];
    __shared__ float s_w[128];

    const int tid = threadIdx.x;
    const int ebase = blockIdx.x * 128;

    if (tid < 128) {
        const int ge = ebase + tid;
        if (ge < N_EDGES) {
            s_src[tid] = edge_src[ge];
            s_dst[tid] = edge_dst[ge];
            s_w[tid]   = edge_w[ge];
        } else {
            s_src[tid] = 0;
            s_dst[tid] = 0;
            s_w[tid]   = 0.f;   // w=0 -> harmless reduction of 0 into node 0
        }
    }
    __syncthreads();

    const int wi   = tid >> 5;
    const int lane = tid & 31;
    const int half = lane >> 4;   // which edge of the pair
    const int li   = lane & 15;   // float4 index within the 64-col row

    #pragma unroll
    for (int it = 0; it < 8; it++) {
        const int le = wi * 16 + it * 2 + half;   // 0..127
        const int   src = s_src[le];
        const int   dst = s_dst[le];
        const float w   = s_w[le];

        const float4 s = *reinterpret_cast<const float4*>(
            support + (size_t)src * OUT_F + li * 4);

        float* o = out + (size_t)dst * OUT_F + li * 4;
        asm volatile("red.global.add.v4.f32 [%0], {%1, %2, %3, %4};"
                     :: "l"(o), "f"(s.x * w), "f"(s.y * w),
                        "f"(s.z * w), "f"(s.w * w)
                     : "memory");
    }
}

// ---------------------------------------------------------------------------
extern "C" void kernel_launch(void* const* d_in, const int* in_sizes, int n_in,
                              void* d_out, int out_size)
{
    const float* features = (const float*)d_in[0];
    const int*   edge_src = (const int*)d_in[1];
    const int*   edge_dst = (const int*)d_in[2];
    const float* edge_w   = (const float*)d_in[3];
    const float* W        = (const float*)d_in[4];
    const float* b        = (const float*)d_in[5];
    float* out = (float*)d_out;

    float* support;
    cudaGetSymbolAddress((void**)&support, g_support);

    // 1) support = features @ W, out = b
    const int gemm_blocks = (N_NODES + TILE_ROWS - 1) / TILE_ROWS;  // 391
    gemm_bias_kernel<<<gemm_blocks, 256>>>(features, W, b, support, out);

    // 2) scatter-add over edges: 128 edges/block
    const int sblocks = (N_EDGES + 127) / 128;                      // 7813
    scatter_kernel<<<sblocks, 256>>>(edge_src, edge_dst, edge_w,
                                     support, out);
}